// round 13
// baseline (speedup 1.0000x reference)
#include <cuda_runtime.h>
#include <cuda_fp16.h>
#include <math.h>

#define MAX_B    512
#define MAX_HALF 50048
#define CPR      16          // chunk CTAs per row
#define NT       256         // threads per CTA
#define GS       16          // pooled values per group (one hot iteration)

// Pooled rows scratch in fp16 (51 MB) — written pass1, read pass2; L2-friendly.
__device__ __half g_pool[(size_t)MAX_B * MAX_HALF];
// Per-(row,chunk) partial moments {sum, sumsq}
__device__ float2 g_part[MAX_B * CPR];

// Pass 1: stream x (ldcs) + noise (L2-resident), pooled fp16 -> g_pool,
// partial (sum,sumsq) per chunk -> g_part.  16 pooled per hot iteration.
__global__ __launch_bounds__(NT)
void pass1_kernel(const float* __restrict__ x,
                  const float* __restrict__ noise,
                  const int*   __restrict__ move_p,
                  int L) {
    const int halfL   = L >> 1;
    const int ngroups = halfL / GS;
    const int gpc     = (ngroups + CPR - 1) / CPR;
    const int row     = blockIdx.x / CPR;
    const int c       = blockIdx.x % CPR;
    const int gc_lo   = c * gpc;
    const int gc_hi   = min(gc_lo + gpc, ngroups);
    const int tid     = threadIdx.x;

    const float* __restrict__ xrow = x + (size_t)row * (size_t)L;
    __half*      __restrict__ prow = g_pool + (size_t)row * (size_t)halfL;

    int mv = __ldg(move_p);
    mv %= L; if (mv < 0) mv += L;

    // Fast-path interval in group space: s0 = 2*GS*g - mv needs
    // s0 >= 0, s0 + 2*GS - 1 < L, and 16B alignment (mv % 4 == 0).
    int fl, fh;
    if ((mv & 3) == 0) {
        fl = (mv + 2 * GS - 1) / (2 * GS);        if (fl > ngroups) fl = ngroups;
        fh = (L + mv - 2 * GS) / (2 * GS) + 1;    if (fh > ngroups) fh = ngroups;
        if (fh < fl) fh = fl;
    } else { fl = 0; fh = 0; }

    int lo = max(gc_lo, fl); if (lo > gc_hi) lo = gc_hi;
    int hi = min(gc_hi, fh); if (hi < lo)    hi = lo;

    float sum = 0.0f, sumsq = 0.0f;

    // ---- scalar edge groups (wrap region) ----
    const int n_low = lo - gc_lo, n_high = gc_hi - hi;
    for (int e = tid; e < n_low + n_high; e += NT) {
        int g = (e < n_low) ? (gc_lo + e) : (hi + (e - n_low));
        int j0 = g * GS;
        #pragma unroll
        for (int k = 0; k < GS; k++) {
            int j = j0 + k;
            int s = 2 * j - mv;
            if (s < 0) s += L; else if (s >= L) s -= L;
            int s1 = s + 1; if (s1 >= L) s1 -= L;
            float p = (xrow[s] + xrow[s1]) * 0.5f
                    + (noise[2 * j] + noise[2 * j + 1]) * 0.02f;
            prow[j] = __float2half_rn(p);
            sum += p; sumsq = fmaf(p, p, sumsq);
        }
    }
    // tail pooled indices (halfL % GS != 0), owned by last chunk
    if (c == CPR - 1) {
        for (int j = ngroups * GS + tid; j < halfL; j += NT) {
            int s = 2 * j - mv;
            if (s < 0) s += L; else if (s >= L) s -= L;
            int s1 = s + 1; if (s1 >= L) s1 -= L;
            float p = (xrow[s] + xrow[s1]) * 0.5f
                    + (noise[2 * j] + noise[2 * j + 1]) * 0.02f;
            prow[j] = __float2half_rn(p);
            sum += p; sumsq = fmaf(p, p, sumsq);
        }
    }

    // ---- hot loop: 8x LDG.128 (x) + 8x LDG.128 (noise,L2) + 2x STG.128 ----
    for (int g = lo + tid; g < hi; g += NT) {
        const int j0 = g * GS;
        const int s0 = 2 * j0 - mv;        // 16B-aligned on fast path
        const int n0 = 2 * j0;             // always 64B-aligned

        float4 xa[8], na[8];
        #pragma unroll
        for (int k = 0; k < 8; k++)
            xa[k] = __ldcs(reinterpret_cast<const float4*>(xrow + s0 + 4 * k));
        #pragma unroll
        for (int k = 0; k < 8; k++)
            na[k] = *reinterpret_cast<const float4*>(noise + n0 + 4 * k);

        float p[GS];
        #pragma unroll
        for (int k = 0; k < 8; k++) {
            p[2 * k]     = (xa[k].x + xa[k].y) * 0.5f + (na[k].x + na[k].y) * 0.02f;
            p[2 * k + 1] = (xa[k].z + xa[k].w) * 0.5f + (na[k].z + na[k].w) * 0.02f;
        }

        uint4 pk0, pk1;
        {
            __half2 h0 = __floats2half2_rn(p[0],  p[1]);
            __half2 h1 = __floats2half2_rn(p[2],  p[3]);
            __half2 h2 = __floats2half2_rn(p[4],  p[5]);
            __half2 h3 = __floats2half2_rn(p[6],  p[7]);
            __half2 h4 = __floats2half2_rn(p[8],  p[9]);
            __half2 h5 = __floats2half2_rn(p[10], p[11]);
            __half2 h6 = __floats2half2_rn(p[12], p[13]);
            __half2 h7 = __floats2half2_rn(p[14], p[15]);
            pk0.x = *reinterpret_cast<unsigned int*>(&h0);
            pk0.y = *reinterpret_cast<unsigned int*>(&h1);
            pk0.z = *reinterpret_cast<unsigned int*>(&h2);
            pk0.w = *reinterpret_cast<unsigned int*>(&h3);
            pk1.x = *reinterpret_cast<unsigned int*>(&h4);
            pk1.y = *reinterpret_cast<unsigned int*>(&h5);
            pk1.z = *reinterpret_cast<unsigned int*>(&h6);
            pk1.w = *reinterpret_cast<unsigned int*>(&h7);
        }
        *reinterpret_cast<uint4*>(prow + j0)     = pk0;
        *reinterpret_cast<uint4*>(prow + j0 + 8) = pk1;

        #pragma unroll
        for (int k = 0; k < GS; k++) {
            sum  += p[k];
            sumsq = fmaf(p[k], p[k], sumsq);
        }
    }

    // ---- deterministic block reduction ----
    __shared__ float s_s[NT / 32], s_q[NT / 32];
    #pragma unroll
    for (int o = 16; o > 0; o >>= 1) {
        sum   += __shfl_down_sync(0xFFFFFFFFu, sum,   o);
        sumsq += __shfl_down_sync(0xFFFFFFFFu, sumsq, o);
    }
    if ((tid & 31) == 0) { s_s[tid >> 5] = sum; s_q[tid >> 5] = sumsq; }
    __syncthreads();
    if (tid == 0) {
        float S = 0.0f, Q = 0.0f;
        #pragma unroll
        for (int w = 0; w < NT / 32; w++) { S += s_s[w]; Q += s_q[w]; }
        g_part[row * CPR + c] = make_float2(S, Q);
    }
}

// Pass 2: fold partials -> mu, 1/sd; fp16 scratch (L2) -> duplicated fp32 out.
__global__ __launch_bounds__(NT)
void pass2_kernel(float* __restrict__ out, int L) {
    const int halfL   = L >> 1;
    const int ngroups = halfL / GS;
    const int gpc     = (ngroups + CPR - 1) / CPR;
    const int row     = blockIdx.x / CPR;
    const int c       = blockIdx.x % CPR;
    const int g_lo    = c * gpc;
    const int g_hi    = min(g_lo + gpc, ngroups);
    const int tid     = threadIdx.x;

    float S = 0.0f, Q = 0.0f;
    #pragma unroll
    for (int k = 0; k < CPR; k++) {
        float2 pp = g_part[row * CPR + k];      // 128 B per row, L2-hot
        S += pp.x; Q += pp.y;
    }
    const float inv_n  = 1.0f / (float)halfL;
    const float mu     = S * inv_n;
    const float inv_sd = rsqrtf(fmaxf(Q * inv_n - mu * mu, 0.0f));

    const __half* __restrict__ prow = g_pool + (size_t)row * (size_t)halfL;
    float*        __restrict__ orow = out + (size_t)row * (size_t)L;

    // hot loop: 2x LDG.128 (scratch) + 8x STG.128 (out, streaming)
    for (int g = g_lo + tid; g < g_hi; g += NT) {
        const int j0 = g * GS;
        uint4 r0 = *reinterpret_cast<const uint4*>(prow + j0);
        uint4 r1 = *reinterpret_cast<const uint4*>(prow + j0 + 8);

        float v[GS];
        {
            float2 f;
            f = __half22float2(*reinterpret_cast<__half2*>(&r0.x)); v[0]=f.x;  v[1]=f.y;
            f = __half22float2(*reinterpret_cast<__half2*>(&r0.y)); v[2]=f.x;  v[3]=f.y;
            f = __half22float2(*reinterpret_cast<__half2*>(&r0.z)); v[4]=f.x;  v[5]=f.y;
            f = __half22float2(*reinterpret_cast<__half2*>(&r0.w)); v[6]=f.x;  v[7]=f.y;
            f = __half22float2(*reinterpret_cast<__half2*>(&r1.x)); v[8]=f.x;  v[9]=f.y;
            f = __half22float2(*reinterpret_cast<__half2*>(&r1.y)); v[10]=f.x; v[11]=f.y;
            f = __half22float2(*reinterpret_cast<__half2*>(&r1.z)); v[12]=f.x; v[13]=f.y;
            f = __half22float2(*reinterpret_cast<__half2*>(&r1.w)); v[14]=f.x; v[15]=f.y;
        }
        #pragma unroll
        for (int k = 0; k < GS; k++) v[k] = (v[k] - mu) * inv_sd;

        float* o = orow + 2 * j0;
        #pragma unroll
        for (int k = 0; k < 8; k++) {
            float4 w = {v[2 * k], v[2 * k], v[2 * k + 1], v[2 * k + 1]};
            __stcs(reinterpret_cast<float4*>(o + 4 * k), w);
        }
    }
    if (c == CPR - 1) {
        for (int j = ngroups * GS + tid; j < halfL; j += NT) {
            float vv = (__half2float(prow[j]) - mu) * inv_sd;
            orow[2 * j]     = vv;
            orow[2 * j + 1] = vv;
        }
    }
}

extern "C" void kernel_launch(void* const* d_in, const int* in_sizes, int n_in,
                              void* d_out, int out_size) {
    const float* x     = (const float*)d_in[0];
    const float* noise = (const float*)d_in[1];
    const int*   move  = (const int*)d_in[2];
    float*       out   = (float*)d_out;

    const int L = in_sizes[1];              // 100000
    const int B = in_sizes[0] / L;          // 512

    pass1_kernel<<<B * CPR, NT>>>(x, noise, move, L);
    pass2_kernel<<<B * CPR, NT>>>(out, L);
}

// round 14
// speedup vs baseline: 1.0042x; 1.0042x over previous
#include <cuda_runtime.h>
#include <cuda_fp16.h>
#include <math.h>

#define MAX_B    512
#define MAX_HALF 50048
#define CPR      16          // chunk CTAs per row
#define NT       256         // threads per CTA
#define GS       16          // pooled values per group (one hot iteration)

// Pooled rows scratch in fp16 (51 MB) — written pass1, read pass2; L2-friendly.
__device__ __half g_pool[(size_t)MAX_B * MAX_HALF];
// Per-(row,chunk) partial moments {sum, sumsq}
__device__ float2 g_part[MAX_B * CPR];

// Pass 1: stream x (ldcs) + noise (L2-resident), pooled fp16 -> g_pool,
// partial (sum,sumsq) per chunk -> g_part.  16 pooled per hot iteration.
__global__ __launch_bounds__(NT)
void pass1_kernel(const float* __restrict__ x,
                  const float* __restrict__ noise,
                  const int*   __restrict__ move_p,
                  int L) {
    const int halfL   = L >> 1;
    const int ngroups = halfL / GS;
    const int gpc     = (ngroups + CPR - 1) / CPR;
    const int row     = blockIdx.x / CPR;
    const int c       = blockIdx.x % CPR;
    const int gc_lo   = c * gpc;
    const int gc_hi   = min(gc_lo + gpc, ngroups);
    const int tid     = threadIdx.x;

    const float* __restrict__ xrow = x + (size_t)row * (size_t)L;
    __half*      __restrict__ prow = g_pool + (size_t)row * (size_t)halfL;

    int mv = __ldg(move_p);
    mv %= L; if (mv < 0) mv += L;

    // Fast-path interval in group space: s0 = 2*GS*g - mv needs
    // s0 >= 0, s0 + 2*GS - 1 < L, and 16B alignment (mv % 4 == 0).
    int fl, fh;
    if ((mv & 3) == 0) {
        fl = (mv + 2 * GS - 1) / (2 * GS);        if (fl > ngroups) fl = ngroups;
        fh = (L + mv - 2 * GS) / (2 * GS) + 1;    if (fh > ngroups) fh = ngroups;
        if (fh < fl) fh = fl;
    } else { fl = 0; fh = 0; }

    int lo = max(gc_lo, fl); if (lo > gc_hi) lo = gc_hi;
    int hi = min(gc_hi, fh); if (hi < lo)    hi = lo;

    float sum = 0.0f, sumsq = 0.0f;

    // ---- scalar edge groups (wrap region) ----
    const int n_low = lo - gc_lo, n_high = gc_hi - hi;
    for (int e = tid; e < n_low + n_high; e += NT) {
        int g = (e < n_low) ? (gc_lo + e) : (hi + (e - n_low));
        int j0 = g * GS;
        #pragma unroll
        for (int k = 0; k < GS; k++) {
            int j = j0 + k;
            int s = 2 * j - mv;
            if (s < 0) s += L; else if (s >= L) s -= L;
            int s1 = s + 1; if (s1 >= L) s1 -= L;
            float p = (xrow[s] + xrow[s1]) * 0.5f
                    + (noise[2 * j] + noise[2 * j + 1]) * 0.02f;
            prow[j] = __float2half_rn(p);
            sum += p; sumsq = fmaf(p, p, sumsq);
        }
    }
    // tail pooled indices (halfL % GS != 0), owned by last chunk
    if (c == CPR - 1) {
        for (int j = ngroups * GS + tid; j < halfL; j += NT) {
            int s = 2 * j - mv;
            if (s < 0) s += L; else if (s >= L) s -= L;
            int s1 = s + 1; if (s1 >= L) s1 -= L;
            float p = (xrow[s] + xrow[s1]) * 0.5f
                    + (noise[2 * j] + noise[2 * j + 1]) * 0.02f;
            prow[j] = __float2half_rn(p);
            sum += p; sumsq = fmaf(p, p, sumsq);
        }
    }

    // ---- hot loop: 8x LDG.128 (x) + 8x LDG.128 (noise,L2) + 2x STG.128 ----
    for (int g = lo + tid; g < hi; g += NT) {
        const int j0 = g * GS;
        const int s0 = 2 * j0 - mv;        // 16B-aligned on fast path
        const int n0 = 2 * j0;             // always 64B-aligned

        float4 xa[8], na[8];
        #pragma unroll
        for (int k = 0; k < 8; k++)
            xa[k] = __ldcs(reinterpret_cast<const float4*>(xrow + s0 + 4 * k));
        #pragma unroll
        for (int k = 0; k < 8; k++)
            na[k] = *reinterpret_cast<const float4*>(noise + n0 + 4 * k);

        float p[GS];
        #pragma unroll
        for (int k = 0; k < 8; k++) {
            p[2 * k]     = (xa[k].x + xa[k].y) * 0.5f + (na[k].x + na[k].y) * 0.02f;
            p[2 * k + 1] = (xa[k].z + xa[k].w) * 0.5f + (na[k].z + na[k].w) * 0.02f;
        }

        uint4 pk0, pk1;
        {
            __half2 h0 = __floats2half2_rn(p[0],  p[1]);
            __half2 h1 = __floats2half2_rn(p[2],  p[3]);
            __half2 h2 = __floats2half2_rn(p[4],  p[5]);
            __half2 h3 = __floats2half2_rn(p[6],  p[7]);
            __half2 h4 = __floats2half2_rn(p[8],  p[9]);
            __half2 h5 = __floats2half2_rn(p[10], p[11]);
            __half2 h6 = __floats2half2_rn(p[12], p[13]);
            __half2 h7 = __floats2half2_rn(p[14], p[15]);
            pk0.x = *reinterpret_cast<unsigned int*>(&h0);
            pk0.y = *reinterpret_cast<unsigned int*>(&h1);
            pk0.z = *reinterpret_cast<unsigned int*>(&h2);
            pk0.w = *reinterpret_cast<unsigned int*>(&h3);
            pk1.x = *reinterpret_cast<unsigned int*>(&h4);
            pk1.y = *reinterpret_cast<unsigned int*>(&h5);
            pk1.z = *reinterpret_cast<unsigned int*>(&h6);
            pk1.w = *reinterpret_cast<unsigned int*>(&h7);
        }
        *reinterpret_cast<uint4*>(prow + j0)     = pk0;
        *reinterpret_cast<uint4*>(prow + j0 + 8) = pk1;

        #pragma unroll
        for (int k = 0; k < GS; k++) {
            sum  += p[k];
            sumsq = fmaf(p[k], p[k], sumsq);
        }
    }

    // ---- deterministic block reduction ----
    __shared__ float s_s[NT / 32], s_q[NT / 32];
    #pragma unroll
    for (int o = 16; o > 0; o >>= 1) {
        sum   += __shfl_down_sync(0xFFFFFFFFu, sum,   o);
        sumsq += __shfl_down_sync(0xFFFFFFFFu, sumsq, o);
    }
    if ((tid & 31) == 0) { s_s[tid >> 5] = sum; s_q[tid >> 5] = sumsq; }
    __syncthreads();
    if (tid == 0) {
        float S = 0.0f, Q = 0.0f;
        #pragma unroll
        for (int w = 0; w < NT / 32; w++) { S += s_s[w]; Q += s_q[w]; }
        g_part[row * CPR + c] = make_float2(S, Q);
    }
}

// Pass 2: fold partials -> mu, 1/sd; fp16 scratch (L2) -> duplicated fp32 out.
__global__ __launch_bounds__(NT)
void pass2_kernel(float* __restrict__ out, int L) {
    const int halfL   = L >> 1;
    const int ngroups = halfL / GS;
    const int gpc     = (ngroups + CPR - 1) / CPR;
    const int row     = blockIdx.x / CPR;
    const int c       = blockIdx.x % CPR;
    const int g_lo    = c * gpc;
    const int g_hi    = min(g_lo + gpc, ngroups);
    const int tid     = threadIdx.x;

    float S = 0.0f, Q = 0.0f;
    #pragma unroll
    for (int k = 0; k < CPR; k++) {
        float2 pp = g_part[row * CPR + k];      // 128 B per row, L2-hot
        S += pp.x; Q += pp.y;
    }
    const float inv_n  = 1.0f / (float)halfL;
    const float mu     = S * inv_n;
    const float inv_sd = rsqrtf(fmaxf(Q * inv_n - mu * mu, 0.0f));

    const __half* __restrict__ prow = g_pool + (size_t)row * (size_t)halfL;
    float*        __restrict__ orow = out + (size_t)row * (size_t)L;

    // hot loop: 2x LDG.128 (scratch) + 8x STG.128 (out, streaming)
    for (int g = g_lo + tid; g < g_hi; g += NT) {
        const int j0 = g * GS;
        uint4 r0 = *reinterpret_cast<const uint4*>(prow + j0);
        uint4 r1 = *reinterpret_cast<const uint4*>(prow + j0 + 8);

        float v[GS];
        {
            float2 f;
            f = __half22float2(*reinterpret_cast<__half2*>(&r0.x)); v[0]=f.x;  v[1]=f.y;
            f = __half22float2(*reinterpret_cast<__half2*>(&r0.y)); v[2]=f.x;  v[3]=f.y;
            f = __half22float2(*reinterpret_cast<__half2*>(&r0.z)); v[4]=f.x;  v[5]=f.y;
            f = __half22float2(*reinterpret_cast<__half2*>(&r0.w)); v[6]=f.x;  v[7]=f.y;
            f = __half22float2(*reinterpret_cast<__half2*>(&r1.x)); v[8]=f.x;  v[9]=f.y;
            f = __half22float2(*reinterpret_cast<__half2*>(&r1.y)); v[10]=f.x; v[11]=f.y;
            f = __half22float2(*reinterpret_cast<__half2*>(&r1.z)); v[12]=f.x; v[13]=f.y;
            f = __half22float2(*reinterpret_cast<__half2*>(&r1.w)); v[14]=f.x; v[15]=f.y;
        }
        #pragma unroll
        for (int k = 0; k < GS; k++) v[k] = (v[k] - mu) * inv_sd;

        float* o = orow + 2 * j0;
        #pragma unroll
        for (int k = 0; k < 8; k++) {
            float4 w = {v[2 * k], v[2 * k], v[2 * k + 1], v[2 * k + 1]};
            __stcs(reinterpret_cast<float4*>(o + 4 * k), w);
        }
    }
    if (c == CPR - 1) {
        for (int j = ngroups * GS + tid; j < halfL; j += NT) {
            float vv = (__half2float(prow[j]) - mu) * inv_sd;
            orow[2 * j]     = vv;
            orow[2 * j + 1] = vv;
        }
    }
}

extern "C" void kernel_launch(void* const* d_in, const int* in_sizes, int n_in,
                              void* d_out, int out_size) {
    const float* x     = (const float*)d_in[0];
    const float* noise = (const float*)d_in[1];
    const int*   move  = (const int*)d_in[2];
    float*       out   = (float*)d_out;

    const int L = in_sizes[1];              // 100000
    const int B = in_sizes[0] / L;          // 512

    pass1_kernel<<<B * CPR, NT>>>(x, noise, move, L);
    pass2_kernel<<<B * CPR, NT>>>(out, L);
}